// round 1
// baseline (speedup 1.0000x reference)
#include <cuda_runtime.h>

// Grouped shifted conv:
//   t = roll(x, +1, axis=W); tp = zero-pad t by 1 on W
//   y[o*16+k, n, m] = sum_{i<64, j<3} tp[o*64+i, n, m+j] * W[i,k,j]
//   out[c, n, m] = y[c, (n-1)%56, m]   (roll +1 along H)
//
// One CTA per (input row n', group o). Shared holds the pre-rotated,
// pre-padded row slab ts[64][58] (so the inner loop is branch-free) and
// W as float4 [i][k]. 224 threads = 16 k * 14 mq, 4 outputs per thread.

#define NTHREADS 224

__global__ __launch_bounds__(NTHREADS) void shiftconv_kernel(
    const float* __restrict__ x,   // (128, 56, 56)
    const float* __restrict__ W,   // (64, 16, 3)
    float* __restrict__ out)       // (32, 56, 56)
{
    __shared__ float  ts[64 * 58];     // tp rows: [i][p], p in 0..57
    __shared__ float4 Ws4[64 * 16];    // W[i][k][0..2], .w unused

    const int np  = blockIdx.x;        // input H-row n'
    const int o   = blockIdx.y;        // channel group
    const int tid = threadIdx.x;

    // Stage W: (i*16+k)*3 == i*48 + k*3  (row-major (64,16,3))
    for (int idx = tid; idx < 64 * 16; idx += NTHREADS) {
        const float* wp = W + idx * 3;
        Ws4[idx] = make_float4(wp[0], wp[1], wp[2], 0.0f);
    }
    // Zero the pad columns of ts
    for (int i = tid; i < 64; i += NTHREADS) {
        ts[i * 58 + 0]  = 0.0f;
        ts[i * 58 + 57] = 0.0f;
    }
    // Stage x row slab with the W-roll folded into the store index:
    // t[(w+1)%56] = x[w]; tp position = t_index + 1.
    const float* xbase = x + (o * 64) * 3136 + np * 56;
    for (int idx = tid; idx < 64 * 56; idx += NTHREADS) {
        const int i = idx / 56;
        const int w = idx - i * 56;
        float v = xbase[i * 3136 + w];
        int w1 = w + 1; if (w1 >= 56) w1 -= 56;
        ts[i * 58 + w1 + 1] = v;
    }
    __syncthreads();

    // k-major thread map keeps W reads near-uniform within a warp.
    const int k  = tid / 14;
    const int mq = tid - k * 14;
    const int m  = mq * 4;             // even -> float2-aligned ts reads

    float a0 = 0.f, a1 = 0.f, a2 = 0.f, a3 = 0.f;
    #pragma unroll
    for (int i = 0; i < 64; i++) {
        const float4 w = Ws4[i * 16 + k];
        const float* row = &ts[i * 58 + m];
        const float2 A = *reinterpret_cast<const float2*>(row);
        const float2 B = *reinterpret_cast<const float2*>(row + 2);
        const float2 C = *reinterpret_cast<const float2*>(row + 4);
        a0 += A.x * w.x + A.y * w.y + B.x * w.z;
        a1 += A.y * w.x + B.x * w.y + B.y * w.z;
        a2 += B.x * w.x + B.y * w.y + C.x * w.z;
        a3 += B.y * w.x + C.x * w.y + C.y * w.z;
    }

    // Output H-roll: y row n' lands at out row (n'+1)%56.
    int nout = np + 1; if (nout >= 56) nout -= 56;
    float4 r = make_float4(a0, a1, a2, a3);
    *reinterpret_cast<float4*>(out + (o * 16 + k) * 3136 + nout * 56 + m) = r;
}

extern "C" void kernel_launch(void* const* d_in, const int* in_sizes, int n_in,
                              void* d_out, int out_size) {
    const float* x = (const float*)d_in[0];   // 128*56*56 = 401408
    const float* W = (const float*)d_in[1];   // 64*16*3   = 3072
    float* out     = (float*)d_out;           // 32*56*56  = 100352

    dim3 grid(56, 2);
    shiftconv_kernel<<<grid, NTHREADS>>>(x, W, out);
}

// round 2
// speedup vs baseline: 1.0091x; 1.0091x over previous
#include <cuda_runtime.h>

// Grouped shifted conv:
//   t = roll(x, +1, axis=W); tp = zero-pad t by 1 on W
//   y[o*16+k, n, m] = sum_{i<64, j<3} tp[o*64+i, n, m+j] * W[i,k,j]
//   out[c, n, m] = y[c, (n-1)%56, m]   (roll +1 along H)
//
// One CTA per (input row n', group o), 896 threads = 4 subgroups of 224.
// Subgroup s reduces input channels i in [16s, 16s+16); partials are summed
// through shared. Row stride 60 keeps float4 shared reads 16B-aligned.

#define NTHREADS 896
#define RSTRIDE  60

__global__ __launch_bounds__(NTHREADS) void shiftconv_kernel(
    const float* __restrict__ x,   // (128, 56, 56)
    const float* __restrict__ W,   // (64, 16, 3)
    float* __restrict__ out)       // (32, 56, 56)
{
    __shared__ float  ts[64 * RSTRIDE];   // tp rows: [i][p], p in 0..57 (58,59 unused)
    __shared__ float4 Ws4[64 * 16];       // W[i][k][0..2], .w unused
    __shared__ float4 psum[3 * 224];      // partials from subgroups 1..3

    const int np  = blockIdx.x;           // input H-row n'
    const int o   = blockIdx.y;           // channel group
    const int tid = threadIdx.x;

    // Stage W: entry (i*16+k) holds W[i][k][0..2]  (row-major (64,16,3))
    for (int idx = tid; idx < 64 * 16; idx += NTHREADS) {
        const float* wp = W + idx * 3;
        Ws4[idx] = make_float4(wp[0], wp[1], wp[2], 0.0f);
    }
    // Zero the pad columns of ts
    if (tid < 64) {
        ts[tid * RSTRIDE + 0]  = 0.0f;
        ts[tid * RSTRIDE + 57] = 0.0f;
    }
    // Stage x row slab: exactly one float4 per thread (64 rows * 14 quads).
    // Roll folded into store index: t[(w+1)%56] = x[w]; tp pos = t_index + 1.
    {
        const float* xbase = x + (o * 64) * 3136 + np * 56;
        const int i  = tid / 14;
        const int q  = tid - i * 14;
        const int w0 = q * 4;
        const float4 v = *reinterpret_cast<const float4*>(xbase + i * 3136 + w0);
        float vv[4] = {v.x, v.y, v.z, v.w};
        #pragma unroll
        for (int e = 0; e < 4; e++) {
            const int wp = w0 + e;
            const int d  = (wp == 55) ? 1 : (wp + 2);
            ts[i * RSTRIDE + d] = vv[e];
        }
    }
    __syncthreads();

    // Subgroup layout: s = i-slice, within: k-major (keeps W reads near-uniform).
    const int s  = tid / 224;
    const int tl = tid - s * 224;
    const int k  = tl / 14;
    const int mq = tl - k * 14;
    const int m  = mq * 4;

    float a0 = 0.f, a1 = 0.f, a2 = 0.f, a3 = 0.f;
    const int ibase = s * 16;
    #pragma unroll
    for (int ii = 0; ii < 16; ii++) {
        const int i = ibase + ii;
        const float4 w = Ws4[i * 16 + k];
        const float* row = &ts[i * RSTRIDE + m];
        const float4 A = *reinterpret_cast<const float4*>(row);      // taps m..m+3
        const float2 C = *reinterpret_cast<const float2*>(row + 4);  // taps m+4,m+5
        a0 += A.x * w.x + A.y * w.y + A.z * w.z;
        a1 += A.y * w.x + A.z * w.y + A.w * w.z;
        a2 += A.z * w.x + A.w * w.y + C.x * w.z;
        a3 += A.w * w.x + C.x * w.y + C.y * w.z;
    }

    if (s > 0) {
        psum[(s - 1) * 224 + tl] = make_float4(a0, a1, a2, a3);
    }
    __syncthreads();

    if (s == 0) {
        const float4 p0 = psum[tl];
        const float4 p1 = psum[224 + tl];
        const float4 p2 = psum[448 + tl];
        a0 += p0.x + p1.x + p2.x;
        a1 += p0.y + p1.y + p2.y;
        a2 += p0.z + p1.z + p2.z;
        a3 += p0.w + p1.w + p2.w;

        // Output H-roll: y row n' lands at out row (n'+1)%56.
        int nout = np + 1; if (nout >= 56) nout -= 56;
        *reinterpret_cast<float4*>(out + (o * 16 + k) * 3136 + nout * 56 + m) =
            make_float4(a0, a1, a2, a3);
    }
}

extern "C" void kernel_launch(void* const* d_in, const int* in_sizes, int n_in,
                              void* d_out, int out_size) {
    const float* x = (const float*)d_in[0];   // 128*56*56 = 401408
    const float* W = (const float*)d_in[1];   // 64*16*3   = 3072
    float* out     = (float*)d_out;           // 32*56*56  = 100352

    dim3 grid(56, 2);
    shiftconv_kernel<<<grid, NTHREADS>>>(x, W, out);
}

// round 3
// speedup vs baseline: 1.1399x; 1.1297x over previous
#include <cuda_runtime.h>

// Grouped shifted conv:
//   t = roll(x, +1, axis=W); tp = zero-pad t by 1 on W
//   y[o*16+k, n, m] = sum_{i<64, j<3} tp[o*64+i, n, m+j] * W[i,k,j]
//   out[c, n, m] = y[c, (n-1)%56, m]   (roll +1 along H)
//
// One CTA per (input row n', group o), 896 threads = 4 subgroups of 224
// (7 warps each). Subgroup s owns input channels i in [16s, 16s+16):
// it stages ONLY its own rows + W slice, passes a subgroup-local named
// barrier, and computes. Only the final cross-subgroup reduction needs a
// block-wide barrier. Row stride 60 keeps float4 shared reads 16B-aligned.

#define NTHREADS 896
#define RSTRIDE  60

__global__ __launch_bounds__(NTHREADS) void shiftconv_kernel(
    const float* __restrict__ x,   // (128, 56, 56)
    const float* __restrict__ W,   // (64, 16, 3)
    float* __restrict__ out)       // (32, 56, 56)
{
    __shared__ float  ts[64 * RSTRIDE];   // tp rows: [i][p], p in 0..57
    __shared__ float4 Ws4[64 * 16];       // W[i][k][0..2], .w unused
    __shared__ float4 psum[3 * 224];      // partials from subgroups 1..3

    const int np  = blockIdx.x;           // input H-row n'
    const int o   = blockIdx.y;           // channel group
    const int tid = threadIdx.x;

    const int s     = tid >> 5 >= 0 ? tid / 224 : 0;  // subgroup 0..3
    const int tl    = tid - s * 224;                   // lane within subgroup
    const int ibase = s * 16;

    // ---- Stage this subgroup's W slice: entries (ibase+il)*16+k ----
    for (int idx = tl; idx < 256; idx += 224) {
        const int il = idx >> 4;
        const int k  = idx & 15;
        const int e  = (ibase + il) * 16 + k;
        const float* wp = W + e * 3;      // row-major (64,16,3)
        Ws4[e] = make_float4(wp[0], wp[1], wp[2], 0.0f);
    }

    // ---- Zero pad columns for this subgroup's rows ----
    if (tl < 16) {
        ts[(ibase + tl) * RSTRIDE + 0]  = 0.0f;
        ts[(ibase + tl) * RSTRIDE + 57] = 0.0f;
    }

    // ---- Stage this subgroup's 16 x-rows (1 float4 per thread) ----
    // Roll folded into store index: t[(w+1)%56] = x[w]; tp pos = t+1.
    // For w<=54 dest = w+2 (contiguous); w=55 wraps to dest 1.
    {
        const int il = tl / 14;
        const int q  = tl - il * 14;
        const int i  = ibase + il;
        const int w0 = q * 4;
        const float4 v = *reinterpret_cast<const float4*>(
            x + (o * 64 + i) * 3136 + np * 56 + w0);
        float* dst = &ts[i * RSTRIDE];
        if (q < 13) {
            // dest w0+2 is 8B-aligned (w0 multiple of 4)
            *reinterpret_cast<float2*>(dst + w0 + 2) = make_float2(v.x, v.y);
            *reinterpret_cast<float2*>(dst + w0 + 4) = make_float2(v.z, v.w);
        } else {
            dst[54] = v.x; dst[55] = v.y; dst[56] = v.z; dst[1] = v.w;
        }
    }

    // ---- Subgroup-local barrier: 7 warps = 224 threads ----
    asm volatile("bar.sync %0, 224;" :: "r"(1 + s) : "memory");

    // k-major within subgroup keeps W reads near-uniform per warp.
    const int k  = tl / 14;
    const int mq = tl - k * 14;
    const int m  = mq * 4;

    float a0 = 0.f, a1 = 0.f, a2 = 0.f, a3 = 0.f;
    #pragma unroll
    for (int ii = 0; ii < 16; ii++) {
        const int i = ibase + ii;
        const float4 w = Ws4[i * 16 + k];
        const float* row = &ts[i * RSTRIDE + m];
        const float4 A = *reinterpret_cast<const float4*>(row);      // taps m..m+3
        const float2 C = *reinterpret_cast<const float2*>(row + 4);  // taps m+4,m+5
        a0 += A.x * w.x + A.y * w.y + A.z * w.z;
        a1 += A.y * w.x + A.z * w.y + A.w * w.z;
        a2 += A.z * w.x + A.w * w.y + C.x * w.z;
        a3 += A.w * w.x + C.x * w.y + C.y * w.z;
    }

    if (s > 0) {
        psum[(s - 1) * 224 + tl] = make_float4(a0, a1, a2, a3);
    }
    __syncthreads();

    if (s == 0) {
        const float4 p0 = psum[tl];
        const float4 p1 = psum[224 + tl];
        const float4 p2 = psum[448 + tl];
        a0 += p0.x + p1.x + p2.x;
        a1 += p0.y + p1.y + p2.y;
        a2 += p0.z + p1.z + p2.z;
        a3 += p0.w + p1.w + p2.w;

        // Output H-roll: y row n' lands at out row (n'+1)%56.
        int nout = np + 1; if (nout >= 56) nout -= 56;
        *reinterpret_cast<float4*>(out + (o * 16 + k) * 3136 + nout * 56 + m) =
            make_float4(a0, a1, a2, a3);
    }
}

extern "C" void kernel_launch(void* const* d_in, const int* in_sizes, int n_in,
                              void* d_out, int out_size) {
    const float* x = (const float*)d_in[0];   // 128*56*56 = 401408
    const float* W = (const float*)d_in[1];   // 64*16*3   = 3072
    float* out     = (float*)d_out;           // 32*56*56  = 100352

    dim3 grid(56, 2);
    shiftconv_kernel<<<grid, NTHREADS>>>(x, W, out);
}

// round 5
// speedup vs baseline: 1.2325x; 1.0812x over previous
#include <cuda_runtime.h>

// Grouped shifted conv:
//   t = roll(x, +1, axis=W); tp = zero-pad t by 1 on W
//   y[o*16+k, n, m] = sum_{i<64, j<3} tp[o*64+i, n, m+j] * W[i,k,j]
//   out[c, n, m] = y[c, (n-1)%56, m]   (roll +1 along H)
//
// Grid (56, 2, 2): one CTA per (input row n', group o, m-half). 224 CTAs,
// 2 resident per SM -> cross-CTA latency hiding. Block 512 = 4 subgroups
// of 128 threads (4 warps, named-barrier friendly); subgroup s owns input
// channels [16s, 16s+16) and stages only its rows of the 30-column m-window
// (stride 32). Subgroups 1-3 finish with a producer bar.arrive and exit;
// subgroup 0 reduces and stores.

#define NTHREADS 512
#define RSTRIDE  32

__global__ __launch_bounds__(NTHREADS) void shiftconv_kernel(
    const float* __restrict__ x,   // (128, 56, 56)
    const float* __restrict__ W,   // (64, 16, 3)
    float* __restrict__ out)       // (32, 56, 56)
{
    __shared__ float  ts[64 * RSTRIDE];   // m-window of tp rows, local cols 0..29
    __shared__ float4 Ws4[64 * 16];       // W[i][k][0..2], .w unused
    __shared__ float4 psum[3 * 112];      // partials from subgroups 1..3

    const int np  = blockIdx.x;           // input H-row n'
    const int o   = blockIdx.y;           // channel group
    const int mh  = blockIdx.z;           // m half: 0 -> cols [0,28), 1 -> [28,56)
    const int tid = threadIdx.x;
    const int s   = tid >> 7;             // subgroup 0..3
    const int tl  = tid & 127;
    const int ibase = s * 16;

    // ---- Stage this subgroup's W slice (its 16 i, all k) ----
    #pragma unroll
    for (int idx = tl; idx < 256; idx += 128) {
        const int e = ibase * 16 + idx;
        const float* wp = W + e * 3;      // row-major (64,16,3)
        Ws4[e] = make_float4(wp[0], wp[1], wp[2], 0.0f);
    }

    // ---- Stage x m-window with roll folded in: tp[p] = x[(p-2) mod 56], tp pads 0 ----
    const float* xrow0 = x + (o * 64 + ibase) * 3136 + np * 56;
    if (mh == 0) {
        // local col c = w + 2 for w in [0,28); c0 = 0 pad; c1 = x[55] (wrap)
        if (tl < 112) {                    // 7 quads/row * 16 rows
            const int il = tl / 7, q = tl - il * 7;
            const int w0 = q * 4;
            const float4 v = *(const float4*)(xrow0 + il * 3136 + w0);
            float* d = &ts[(ibase + il) * RSTRIDE + w0 + 2];
            *(float2*)(d)     = make_float2(v.x, v.y);
            *(float2*)(d + 2) = make_float2(v.z, v.w);
        } else {
            const int il = tl - 112;       // 16 rows
            float* d = &ts[(ibase + il) * RSTRIDE];
            d[0] = 0.0f;
            d[1] = xrow0[il * 3136 + 55];
        }
    } else {
        // local col c = w - 26 for w in [26,55); c29 = 0 pad (tp[57])
        const int il = tl >> 3, q = tl & 7;       // 8 quads/row * 16 rows = 128
        const int w0 = 24 + q * 4;
        const float4 v = *(const float4*)(xrow0 + il * 3136 + w0);
        float* d = &ts[(ibase + il) * RSTRIDE];
        if (q == 0) {
            d[0] = v.z; d[1] = v.w;               // w = 26, 27
            d[29] = 0.0f;                         // pad
        } else if (q == 7) {
            d[26] = v.x; d[27] = v.y; d[28] = v.z; // w = 52..54 (55 dropped)
        } else {
            const int c0 = w0 - 26;                // even -> 8B aligned
            *(float2*)(d + c0)     = make_float2(v.x, v.y);
            *(float2*)(d + c0 + 2) = make_float2(v.z, v.w);
        }
    }

    // ---- Subgroup-local barrier: 4 warps = 128 threads ----
    asm volatile("bar.sync %0, 128;" :: "r"(1 + s) : "memory");

    const int k  = tl / 7;                // valid for tl < 112
    const int mq = tl - k * 7;
    const int m  = mq * 4;                // local col

    float a0 = 0.f, a1 = 0.f, a2 = 0.f, a3 = 0.f;
    if (tl < 112) {
        #pragma unroll
        for (int ii = 0; ii < 16; ii++) {
            const int i = ibase + ii;
            const float4 w = Ws4[i * 16 + k];
            const float* row = &ts[i * RSTRIDE + m];
            const float4 A = *(const float4*)(row);      // taps m..m+3
            const float2 C = *(const float2*)(row + 4);  // taps m+4, m+5
            a0 += A.x * w.x + A.y * w.y + A.z * w.z;
            a1 += A.y * w.x + A.z * w.y + A.w * w.z;
            a2 += A.z * w.x + A.w * w.y + C.x * w.z;
            a3 += A.w * w.x + C.x * w.y + C.y * w.z;
        }
    }

    if (s > 0) {
        if (tl < 112) psum[(s - 1) * 112 + tl] = make_float4(a0, a1, a2, a3);
        // Producer arrive: post partials and exit (frees 12 warps early).
        asm volatile("bar.arrive 5, %0;" :: "n"(NTHREADS) : "memory");
        return;
    }

    // Subgroup 0: wait for all producers, then reduce + store.
    asm volatile("bar.sync 5, %0;" :: "n"(NTHREADS) : "memory");

    if (tl < 112) {
        const float4 p0 = psum[tl];
        const float4 p1 = psum[112 + tl];
        const float4 p2 = psum[224 + tl];
        a0 += p0.x + p1.x + p2.x;
        a1 += p0.y + p1.y + p2.y;
        a2 += p0.z + p1.z + p2.z;
        a3 += p0.w + p1.w + p2.w;

        int nout = np + 1; if (nout >= 56) nout -= 56;   // output H-roll
        *reinterpret_cast<float4*>(
            out + (o * 16 + k) * 3136 + nout * 56 + mh * 28 + m) =
            make_float4(a0, a1, a2, a3);
    }
}

extern "C" void kernel_launch(void* const* d_in, const int* in_sizes, int n_in,
                              void* d_out, int out_size) {
    const float* x = (const float*)d_in[0];   // 128*56*56 = 401408
    const float* W = (const float*)d_in[1];   // 64*16*3   = 3072
    float* out     = (float*)d_out;           // 32*56*56  = 100352

    dim3 grid(56, 2, 2);
    shiftconv_kernel<<<grid, NTHREADS>>>(x, W, out);
}